// round 11
// baseline (speedup 1.0000x reference)
#include <cuda_runtime.h>
#include <math.h>

#define H 64
#define W 64
#define C 256
#define P 7
#define NUM_ROIS 256
#define NBINS (NUM_ROIS * P * P)   // 12544
#define FC (W * C)                 // floats per x-row (16384)
#define NKEY 4096                  // 64 x 64 spatial buckets
#define MAIN_CTAS 296
#define MAIN_THREADS 512

// ---- static scratch (no allocation allowed) ----
__device__ int  g_hist[NKEY];      // zero-init; re-zeroed by scatter each call
__device__ int  g_offs[NKEY];
__device__ int2 g_recs[NBINS];     // unsorted {packed, outBin}
__device__ int2 g_sorted[NBINS];   // sorted by spatial key

__device__ __forceinline__ float4 fmax4(float4 a, float4 b) {
    a.x = fmaxf(a.x, b.x);
    a.y = fmaxf(a.y, b.y);
    a.z = fmaxf(a.z, b.z);
    a.w = fmaxf(a.w, b.w);
    return a;
}

// K1: per-bin bounds (exact reference math) + spatial histogram.
// packed = ys | (xs<<6) | (xlen<<12) | (ylen<<18); key = packed & 4095.
__global__ __launch_bounds__(256) void bins_kernel(const float* __restrict__ rois) {
    const int bin = blockIdx.x * 256 + (int)threadIdx.x;
    if (bin >= NBINS) return;
    const int r  = bin / (P * P);
    const int ij = bin - r * (P * P);
    const int i  = ij / P;
    const int j  = ij - i * P;

    const float x1 = __ldg(&rois[r * 4 + 0]);
    const float y1 = __ldg(&rois[r * 4 + 1]);
    const float x2 = __ldg(&rois[r * 4 + 2]);
    const float y2 = __ldg(&rois[r * 4 + 3]);

    const int lox   = (int)floorf(x1 * (float)H);
    const int hix   = (int)ceilf(x2 * (float)H);
    const int spanx = max(hix - lox, 1);
    int xs          = lox + (i * spanx) / P;
    const int xe    = lox + ((i + 1) * spanx + (P - 1)) / P;
    const int xlen  = max(xe - xs, 1);
    xs = min(max(xs, 0), H - 1);

    const int loy   = (int)floorf(y1 * (float)W);
    const int hiy   = (int)ceilf(y2 * (float)W);
    const int spany = max(hiy - loy, 1);
    int ys          = loy + (j * spany) / P;
    const int ye    = loy + ((j + 1) * spany + (P - 1)) / P;
    const int ylen  = max(ye - ys, 1);
    ys = min(max(ys, 0), W - 1);

    const int packed = ys | (xs << 6) | (xlen << 12) | (ylen << 18);
    g_recs[bin] = make_int2(packed, bin);
    atomicAdd(&g_hist[packed & (NKEY - 1)], 1);
}

// K2: exclusive prefix sum over the 4096-bucket histogram (1 block).
__global__ __launch_bounds__(1024) void scan_kernel() {
    __shared__ int ssum[1024];
    const int t = (int)threadIdx.x;
    const int v0 = g_hist[t * 4 + 0];
    const int v1 = g_hist[t * 4 + 1];
    const int v2 = g_hist[t * 4 + 2];
    const int v3 = g_hist[t * 4 + 3];
    const int s1 = v0, s2 = v0 + v1, s3 = s2 + v2, s4 = s3 + v3;
    ssum[t] = s4;
    __syncthreads();
    for (int d = 1; d < 1024; d <<= 1) {
        const int add = (t >= d) ? ssum[t - d] : 0;
        __syncthreads();
        ssum[t] += add;
        __syncthreads();
    }
    const int excl = (t == 0) ? 0 : ssum[t - 1];
    g_offs[t * 4 + 0] = excl;
    g_offs[t * 4 + 1] = excl + s1;
    g_offs[t * 4 + 2] = excl + s2;
    g_offs[t * 4 + 3] = excl + s3;
}

// K3: scatter into sorted order; re-zero histogram for the next graph replay.
__global__ __launch_bounds__(256) void scatter_kernel() {
    const int idx = blockIdx.x * 256 + (int)threadIdx.x;
    if (idx < NBINS) {
        const int2 rec = g_recs[idx];
        const int key  = rec.x & (NKEY - 1);
        const int pos  = atomicAdd(&g_offs[key], 1);
        g_sorted[pos] = rec;
    }
    if (idx < NKEY) g_hist[idx] = 0;
}

// K4: 296 CTAs x 512 thr. CTA k owns contiguous sorted-bin run; its 16 warps
// stride the run (window of 16 adjacent bins -> shared L1 footprint).
// Warp = one bin; lane = channel quads c4 and c4+128 (coalesced 512B loads).
// y-loop: ylen/2 clean pairs + warp-uniform odd tail (zero duplicate loads).
__global__ __launch_bounds__(MAIN_THREADS, 2) void roi_pool_kernel(
    const float* __restrict__ feat,   // (H, W, C)
    float* __restrict__ out)          // (NUM_ROIS, P, P, C)
{
    const int cta   = blockIdx.x;
    const int start = (int)(((long long)cta * NBINS) / MAIN_CTAS);
    const int end   = (int)(((long long)(cta + 1) * NBINS) / MAIN_CTAS);
    const int wid   = (int)threadIdx.x >> 5;
    const int lane  = (int)threadIdx.x & 31;
    const int c4    = lane << 2;

    const float NEG = -INFINITY;

    for (int idx = start + wid; idx < end; idx += MAIN_THREADS / 32) {
        const int2 rec  = g_sorted[idx];
        const int  pk   = rec.x;
        const int  ys   = pk & 63;
        const int  xs   = (pk >> 6) & 63;
        const int  xlen = (pk >> 12) & 63;
        const int  ylen = (pk >> 18) & 63;

        const int  npairs = ylen >> 1;
        const bool ytail  = (ylen & 1) != 0;
        const int  tailo  = (npairs * 2) * C;

        float4 aL = make_float4(NEG, NEG, NEG, NEG);
        float4 aH = aL;

        const float* rowp = feat + (size_t)xs * FC + (size_t)ys * C + c4;

        for (int sx = 0; sx < xlen; ++sx) {
            const float* p = rowp;
            for (int sp = 0; sp < npairs; ++sp) {
                const float4 vL0 = *reinterpret_cast<const float4*>(p);
                const float4 vH0 = *reinterpret_cast<const float4*>(p + 128);
                const float4 vL1 = *reinterpret_cast<const float4*>(p + C);
                const float4 vH1 = *reinterpret_cast<const float4*>(p + C + 128);
                aL = fmax4(aL, fmax4(vL0, vL1));
                aH = fmax4(aH, fmax4(vH0, vH1));
                p += 2 * C;
            }
            if (ytail) {
                const float* t = rowp + tailo;
                aL = fmax4(aL, *reinterpret_cast<const float4*>(t));
                aH = fmax4(aH, *reinterpret_cast<const float4*>(t + 128));
            }
            rowp += FC;
        }

        float* op = out + (size_t)rec.y * C + c4;
        *reinterpret_cast<float4*>(op)       = aL;
        *reinterpret_cast<float4*>(op + 128) = aH;
    }
}

extern "C" void kernel_launch(void* const* d_in, const int* in_sizes, int n_in,
                              void* d_out, int out_size) {
    const float* feat = (const float*)d_in[0];
    const float* rois = (const float*)d_in[1];
    if (n_in >= 2 && in_sizes[0] == NUM_ROIS * 4 && in_sizes[1] == H * W * C) {
        feat = (const float*)d_in[1];
        rois = (const float*)d_in[0];
    }
    float* out = (float*)d_out;

    bins_kernel<<<(NBINS + 255) / 256, 256>>>(rois);
    scan_kernel<<<1, 1024>>>();
    scatter_kernel<<<(NBINS + 255) / 256, 256>>>();
    roi_pool_kernel<<<MAIN_CTAS, MAIN_THREADS>>>(feat, out);
}

// round 12
// speedup vs baseline: 1.4116x; 1.4116x over previous
#include <cuda_runtime.h>
#include <math.h>

#define H 64
#define W 64
#define C 256
#define P 7
#define NUM_ROIS 256
#define FC (W * C)   // floats per x-row (16384)

__device__ __forceinline__ float4 fmax4(float4 a, float4 b) {
    a.x = fmaxf(a.x, b.x);
    a.y = fmaxf(a.y, b.y);
    a.z = fmaxf(a.z, b.z);
    a.w = fmaxf(a.w, b.w);
    return a;
}

// One block per (roi, i, j) bin; 64 threads = 64 float4 channel groups.
// Dispatch on bin extent to CONSTANT-trip-count tap grids so all loads of a
// bin issue back-to-back (1-2 latency exposures instead of ~xlen):
//   2x2 grid  (xlen,ylen <= 2):  4 taps
//   4x4 grid  (xlen,ylen <= 4): 16 taps   (~80% of bins)
//   fallback  (up to 5 wide):   5-tap rows x dynamic xlen
// Clamped taps duplicate the last valid row/col: same address -> L1 hit,
// and duplicates never change a max.
__global__ __launch_bounds__(64) void roi_pool_kernel(
    const float* __restrict__ feat,   // (H, W, C)
    const float* __restrict__ rois,   // (NUM_ROIS, 4) = x1,y1,x2,y2
    float* __restrict__ out)          // (NUM_ROIS, P, P, C)
{
    const int b  = blockIdx.x;        // r*49 + i*7 + j
    const int r  = b / (P * P);
    const int ij = b - r * (P * P);
    const int i  = ij / P;
    const int j  = ij - i * P;

    const int c4 = (int)threadIdx.x << 2;   // channel quad

    const float x1 = __ldg(&rois[r * 4 + 0]);
    const float y1 = __ldg(&rois[r * 4 + 1]);
    const float x2 = __ldg(&rois[r * 4 + 2]);
    const float y2 = __ldg(&rois[r * 4 + 3]);

    // exact reference bin math; in-range for 0<=x1<x2<=1
    const int lox   = (int)floorf(x1 * (float)H);
    const int hix   = (int)ceilf(x2 * (float)H);
    const int spanx = max(hix - lox, 1);
    const int xs    = lox + (i * spanx) / P;
    const int xe    = lox + ((i + 1) * spanx + (P - 1)) / P;
    const int xlen  = max(xe - xs, 1);

    const int loy   = (int)floorf(y1 * (float)W);
    const int hiy   = (int)ceilf(y2 * (float)W);
    const int spany = max(hiy - loy, 1);
    const int ys    = loy + (j * spany) / P;
    const int ye    = loy + ((j + 1) * spany + (P - 1)) / P;
    const int ylen  = max(ye - ys, 1);

    const float NEG = -INFINITY;
    float4 acc = make_float4(NEG, NEG, NEG, NEG);

    const float* base = feat + (size_t)xs * FC + (size_t)ys * C + c4;

    const int xm = xlen - 1;
    const int ym = ylen - 1;

    if (xlen <= 4 && ylen <= 4) {
        // clamped col offsets (floats) and row pointers
        const int co1 = min(1, ym) * C;
        const int co2 = min(2, ym) * C;
        const int co3 = min(3, ym) * C;
        const float* r0 = base;
        const float* r1 = base + (size_t)min(1, xm) * FC;
        const float* r2 = base + (size_t)min(2, xm) * FC;
        const float* r3 = base + (size_t)min(3, xm) * FC;

        if (xlen <= 2 && ylen <= 2) {
            // 2x2: 4 taps, one issue batch
            const float4 v00 = *reinterpret_cast<const float4*>(r0);
            const float4 v01 = *reinterpret_cast<const float4*>(r0 + co1);
            const float4 v10 = *reinterpret_cast<const float4*>(r1);
            const float4 v11 = *reinterpret_cast<const float4*>(r1 + co1);
            acc = fmax4(fmax4(v00, v01), fmax4(v10, v11));
        } else {
            // 4x4: 16 taps, fully batched
            const float4 a00 = *reinterpret_cast<const float4*>(r0);
            const float4 a01 = *reinterpret_cast<const float4*>(r0 + co1);
            const float4 a02 = *reinterpret_cast<const float4*>(r0 + co2);
            const float4 a03 = *reinterpret_cast<const float4*>(r0 + co3);
            const float4 a10 = *reinterpret_cast<const float4*>(r1);
            const float4 a11 = *reinterpret_cast<const float4*>(r1 + co1);
            const float4 a12 = *reinterpret_cast<const float4*>(r1 + co2);
            const float4 a13 = *reinterpret_cast<const float4*>(r1 + co3);
            const float4 a20 = *reinterpret_cast<const float4*>(r2);
            const float4 a21 = *reinterpret_cast<const float4*>(r2 + co1);
            const float4 a22 = *reinterpret_cast<const float4*>(r2 + co2);
            const float4 a23 = *reinterpret_cast<const float4*>(r2 + co3);
            const float4 a30 = *reinterpret_cast<const float4*>(r3);
            const float4 a31 = *reinterpret_cast<const float4*>(r3 + co1);
            const float4 a32 = *reinterpret_cast<const float4*>(r3 + co2);
            const float4 a33 = *reinterpret_cast<const float4*>(r3 + co3);
            const float4 m0 = fmax4(fmax4(a00, a01), fmax4(a02, a03));
            const float4 m1 = fmax4(fmax4(a10, a11), fmax4(a12, a13));
            const float4 m2 = fmax4(fmax4(a20, a21), fmax4(a22, a23));
            const float4 m3 = fmax4(fmax4(a30, a31), fmax4(a32, a33));
            acc = fmax4(fmax4(m0, m1), fmax4(m2, m3));
        }
    } else {
        // fallback: 5 clamped taps per x-row (ylen <= 5 for these ROI sizes;
        // clamping keeps it correct for any ylen <= 5), dynamic xlen
        const int co1 = min(1, ym) * C;
        const int co2 = min(2, ym) * C;
        const int co3 = min(3, ym) * C;
        const int co4 = min(4, ym) * C;
        const float* rp = base;
        for (int sx = 0; sx < xlen; ++sx) {
            const float4 v0 = *reinterpret_cast<const float4*>(rp);
            const float4 v1 = *reinterpret_cast<const float4*>(rp + co1);
            const float4 v2 = *reinterpret_cast<const float4*>(rp + co2);
            const float4 v3 = *reinterpret_cast<const float4*>(rp + co3);
            const float4 v4 = *reinterpret_cast<const float4*>(rp + co4);
            acc = fmax4(acc, fmax4(fmax4(v0, v1), fmax4(v2, fmax4(v3, v4))));
            rp += FC;
        }
        // safety for ylen > 5 (not expected with given ROI distribution)
        for (int sy = 5; sy < ylen; ++sy) {
            const float* p = base + (size_t)sy * C;
            for (int sx = 0; sx < xlen; ++sx) {
                acc = fmax4(acc, *reinterpret_cast<const float4*>(p));
                p += FC;
            }
        }
    }

    float* op = out + ((size_t)b * C) + c4;
    *reinterpret_cast<float4*>(op) = acc;
}

extern "C" void kernel_launch(void* const* d_in, const int* in_sizes, int n_in,
                              void* d_out, int out_size) {
    const float* feat = (const float*)d_in[0];
    const float* rois = (const float*)d_in[1];
    if (n_in >= 2 && in_sizes[0] == NUM_ROIS * 4 && in_sizes[1] == H * W * C) {
        feat = (const float*)d_in[1];
        rois = (const float*)d_in[0];
    }
    float* out = (float*)d_out;

    roi_pool_kernel<<<NUM_ROIS * P * P, 64>>>(feat, rois, out);
}